// round 5
// baseline (speedup 1.0000x reference)
#include <cuda_runtime.h>
#include <cstdint>

#define Hh 192
#define Ww 192
#define HWsz (192*192)
#define Cc 32
#define Tt 8
#define KK 9

// Channels-last scratch: [B][T][HW][C]  (75.5 MB)
__device__ float g_scratch[(size_t)2 * Tt * HWsz * Cc];
// Weights in mma fragment order: [t][tap][kstep][ntile][lane][reg]
__device__ uint32_t g_wfrag[(size_t)Tt * KK * 4 * 4 * 32 * 2];

__device__ __forceinline__ uint32_t f2tf32(float v) {
    uint32_t u;
    asm("cvt.rna.tf32.f32 %0, %1;" : "=r"(u) : "f"(v));
    return u;
}

__device__ __forceinline__ void mma_tf32(float* c, uint32_t a0, uint32_t a1,
                                         uint32_t a2, uint32_t a3,
                                         uint32_t b0, uint32_t b1) {
    asm volatile(
        "mma.sync.aligned.m16n8k8.row.col.f32.tf32.tf32.f32 "
        "{%0,%1,%2,%3}, {%4,%5,%6,%7}, {%8,%9}, {%0,%1,%2,%3};"
        : "+f"(c[0]), "+f"(c[1]), "+f"(c[2]), "+f"(c[3])
        : "r"(a0), "r"(a1), "r"(a2), "r"(a3), "r"(b0), "r"(b1));
}

// ---------- Kernel 0: weights -> tf32 fragments (grid = 8 x 4) ----------
__global__ __launch_bounds__(256) void wprep_k(const float* __restrict__ weight) {
    const int t = blockIdx.x;
    const int part = blockIdx.y;            // 0..3, 9 iters each
    for (int it = part * 9; it < part * 9 + 9; it++) {
        const int j = it * 256 + threadIdx.x;        // j < 9216
        const int reg   = j & 1;
        const int lane  = (j >> 1) & 31;
        const int ntile = (j >> 6) & 3;
        const int kstep = (j >> 8) & 3;
        const int tap   = j >> 10;                   // 0..8
        const int cin  = kstep * 8 + (lane & 3) + reg * 4;
        const int cout = ntile * 8 + (lane >> 2);
        const float v = weight[((size_t)(t * Cc + cout) * Cc + cin) * KK + tap];
        g_wfrag[(size_t)t * 9216 + j] = f2tf32(v);
    }
}

// ---------- Kernel 1: feat [B,C,T,H,W] -> scratch [B,T,HW,C] ----------
__global__ __launch_bounds__(256) void transpose_k(const float* __restrict__ feat) {
    __shared__ float tl[32][33];
    const int bt = blockIdx.y;
    const int b = bt >> 3, t = bt & 7;
    const int hw0 = blockIdx.x * 32;
    const int x = threadIdx.x & 31;
    const int y = threadIdx.x >> 5;
    #pragma unroll
    for (int j = 0; j < 4; j++) {
        const int c = y + j * 8;
        tl[c][x] = feat[((size_t)(b * Cc + c) * Tt + t) * HWsz + hw0 + x];
    }
    __syncthreads();
    #pragma unroll
    for (int j = 0; j < 4; j++) {
        const int hwl = y + j * 8;
        g_scratch[((size_t)bt * HWsz + hw0 + hwl) * Cc + x] = tl[x][hwl];
    }
}

// ---------- Kernel 2: fused deform-sample + mma.sync tf32 GEMM ----------
// smem: [Wfrag 36864B][A slabs 8 x 32x36 floats = 36864B, reused as Dtile 32x260]
#define SM_W 0
#define SM_A 36864
#define SM_TOTAL 73728
#define APAD 36
#define DPAD 260

__global__ __launch_bounds__(256, 3) void dcn_main(
    const float* __restrict__ offset,   // [B, 18, T, H, W]
    float* __restrict__ out)            // [B, 32, T, H, W]
{
    extern __shared__ char smem[];
    uint32_t* swf = (uint32_t*)(smem + SM_W);
    const int tid  = threadIdx.x;
    const int wid  = tid >> 5;
    const int lane = tid & 31;
    const int bt = blockIdx.y;
    const int b = bt >> 3, t = bt & 7;
    const int pix0  = blockIdx.x * 256;
    const int pixw0 = pix0 + wid * 32;

    // Copy this t's weight fragments (9216 u32) to smem, coalesced.
    {
        const uint4* src = (const uint4*)(g_wfrag + (size_t)t * 9216);
        uint4* dst = (uint4*)swf;
        #pragma unroll
        for (int i = 0; i < 9; i++) dst[tid + 256 * i] = src[tid + 256 * i];
    }
    __syncthreads();

    uint32_t* sa = (uint32_t*)(smem + SM_A) + wid * (32 * APAD);  // warp-private A slab
    const float* sbase = g_scratch + (size_t)bt * HWsz * Cc + (lane & 7) * 4;
    const float* offb = offset + ((size_t)b * 2 * KK * Tt + t) * HWsz + pixw0 + lane;

    // This lane's own pixel geometry (for phase A param computation).
    const int mypix = pixw0 + lane;
    const int myh = (int)((unsigned)mypix / Ww);
    const int myw = mypix - myh * Ww;

    float acc[2][4][4];
    #pragma unroll
    for (int s = 0; s < 2; s++)
        #pragma unroll
        for (int n = 0; n < 4; n++)
            #pragma unroll
            for (int r = 0; r < 4; r++) acc[s][n][r] = 0.f;

    #pragma unroll 1
    for (int k = 0; k < KK; k++) {
        // ---- Phase A: per-lane (lane == pixel) bilinear params for tap k ----
        const float dy = offb[(size_t)(2 * k)     * Tt * HWsz];
        const float dx = offb[(size_t)(2 * k + 1) * Tt * HWsz];
        const int dky = k / 3 - 1;
        const int dkx = k - (k / 3) * 3 - 1;
        const float ys = dy + (float)(myh + dky);
        const float xs = dx + (float)(myw + dkx);

        const float y0f = floorf(ys), x0f = floorf(xs);
        const int iy0 = (int)y0f, ix0 = (int)x0f;
        const int iy1 = iy0 + 1,  ix1 = ix0 + 1;
        const float fy = ys - y0f, fx = xs - x0f;
        const float gy = 1.f - fy, gx = 1.f - fx;

        const bool vy0 = (unsigned)iy0 < Hh;
        const bool vy1 = (unsigned)iy1 < Hh;
        const bool vx0 = (unsigned)ix0 < Ww;
        const bool vx1 = (unsigned)ix1 < Ww;
        const int cy0 = min(max(iy0, 0), Hh - 1);
        const int cy1 = min(max(iy1, 0), Hh - 1);
        const int cx0 = min(max(ix0, 0), Ww - 1);
        const int cx1 = min(max(ix1, 0), Ww - 1);

        const float w00 = (vy0 && vx0) ? gy * gx : 0.f;
        const float w01 = (vy0 && vx1) ? gy * fx : 0.f;
        const float w10 = (vy1 && vx0) ? fy * gx : 0.f;
        const float w11 = (vy1 && vx1) ? fy * fx : 0.f;

        const int i00 = cy0 * Ww + cx0;
        const int i01 = cy0 * Ww + cx1;
        const int i10 = cy1 * Ww + cx0;
        const int i11 = cy1 * Ww + cx1;

        // ---- Phase B: gather + combine, 4 pixels per iteration ----
        #pragma unroll 2
        for (int p = 0; p < 8; p++) {
            const int srcl = p * 4 + (lane >> 3);

            const int j00 = __shfl_sync(0xffffffffu, i00, srcl);
            const int j01 = __shfl_sync(0xffffffffu, i01, srcl);
            const int j10 = __shfl_sync(0xffffffffu, i10, srcl);
            const int j11 = __shfl_sync(0xffffffffu, i11, srcl);
            const float u00 = __shfl_sync(0xffffffffu, w00, srcl);
            const float u01 = __shfl_sync(0xffffffffu, w01, srcl);
            const float u10 = __shfl_sync(0xffffffffu, w10, srcl);
            const float u11 = __shfl_sync(0xffffffffu, w11, srcl);

            const float4 a00 = *(const float4*)(sbase + (size_t)j00 * Cc);
            const float4 a01 = *(const float4*)(sbase + (size_t)j01 * Cc);
            const float4 a10 = *(const float4*)(sbase + (size_t)j10 * Cc);
            const float4 a11 = *(const float4*)(sbase + (size_t)j11 * Cc);

            const float v0 = fmaf(u00, a00.x, fmaf(u01, a01.x, fmaf(u10, a10.x, u11 * a11.x)));
            const float v1 = fmaf(u00, a00.y, fmaf(u01, a01.y, fmaf(u10, a10.y, u11 * a11.y)));
            const float v2 = fmaf(u00, a00.z, fmaf(u01, a01.z, fmaf(u10, a10.z, u11 * a11.z)));
            const float v3 = fmaf(u00, a00.w, fmaf(u01, a01.w, fmaf(u10, a10.w, u11 * a11.w)));

            uint4 u; u.x = f2tf32(v0); u.y = f2tf32(v1); u.z = f2tf32(v2); u.w = f2tf32(v3);
            *(uint4*)(sa + srcl * APAD + (lane & 7) * 4) = u;
        }
        __syncwarp();

        // ---- MMA: D[32x32] += A[32x32] * W_k^T ----
        const int r0 = lane >> 2;
        const int c0 = lane & 3;
        #pragma unroll
        for (int ks = 0; ks < 4; ks++) {
            const int cb = ks * 8 + c0;
            const uint32_t a00_ = sa[r0 * APAD + cb];
            const uint32_t a01_ = sa[(r0 + 8) * APAD + cb];
            const uint32_t a02_ = sa[r0 * APAD + cb + 4];
            const uint32_t a03_ = sa[(r0 + 8) * APAD + cb + 4];
            const uint32_t a10_ = sa[(r0 + 16) * APAD + cb];
            const uint32_t a11_ = sa[(r0 + 24) * APAD + cb];
            const uint32_t a12_ = sa[(r0 + 16) * APAD + cb + 4];
            const uint32_t a13_ = sa[(r0 + 24) * APAD + cb + 4];
            #pragma unroll
            for (int nt = 0; nt < 4; nt++) {
                const uint2 bb = *(const uint2*)(swf + (((k * 4 + ks) * 4 + nt) << 6) + lane * 2);
                mma_tf32(acc[0][nt], a00_, a01_, a02_, a03_, bb.x, bb.y);
                mma_tf32(acc[1][nt], a10_, a11_, a12_, a13_, bb.x, bb.y);
            }
        }
        __syncwarp();
    }

    // Epilogue: stage D in smem (reusing A region), then coalesced STG.128.
    __syncthreads();
    float* sd = (float*)(smem + SM_A);
    {
        const int pixb = wid * 32 + (lane >> 2);
        #pragma unroll
        for (int s = 0; s < 2; s++) {
            #pragma unroll
            for (int nt = 0; nt < 4; nt++) {
                const int row = nt * 8 + 2 * (lane & 3);
                const int px = pixb + s * 16;
                sd[row * DPAD + px]           = acc[s][nt][0];
                sd[(row + 1) * DPAD + px]     = acc[s][nt][1];
                sd[row * DPAD + px + 8]       = acc[s][nt][2];
                sd[(row + 1) * DPAD + px + 8] = acc[s][nt][3];
            }
        }
    }
    __syncthreads();
    #pragma unroll
    for (int i = 0; i < 8; i++) {
        const int j = tid + 256 * i;       // j < 2048
        const int row = j >> 6;            // cout
        const int q = j & 63;              // float4 index within 256 pixels
        const float4 v = *(const float4*)(sd + row * DPAD + q * 4);
        *(float4*)(out + ((size_t)(b * Cc + row) * Tt + t) * HWsz + pix0 + q * 4) = v;
    }
}

extern "C" void kernel_launch(void* const* d_in, const int* in_sizes, int n_in,
                              void* d_out, int out_size) {
    const float* feat   = (const float*)d_in[0];
    const float* offset = (const float*)d_in[1];
    const float* weight = (const float*)d_in[2];
    float* out = (float*)d_out;

    cudaFuncSetAttribute(dcn_main, cudaFuncAttributeMaxDynamicSharedMemorySize, SM_TOTAL);

    wprep_k<<<dim3(Tt, 4), 256>>>(weight);
    transpose_k<<<dim3(HWsz / 32, 16), 256>>>(feat);
    dcn_main<<<dim3(HWsz / 256, 16), 256, SM_TOTAL>>>(offset, out);
}

// round 6
// speedup vs baseline: 1.0799x; 1.0799x over previous
#include <cuda_runtime.h>
#include <cuda_fp16.h>
#include <cstdint>

#define Hh 192
#define Ww 192
#define HWsz (192*192)
#define Cc 32
#define Tt 8
#define KK 9

// Channels-last fp16 scratch: [B][T][HW][C]  (37.7 MB)
__device__ __half g_scratch_h[(size_t)2 * Tt * HWsz * Cc];
// Weights in mma fragment order: [t][tap][kstep][ntile][lane][reg]
__device__ uint32_t g_wfrag[(size_t)Tt * KK * 4 * 4 * 32 * 2];

__device__ __forceinline__ uint32_t f2tf32(float v) {
    uint32_t u;
    asm("cvt.rna.tf32.f32 %0, %1;" : "=r"(u) : "f"(v));
    return u;
}

__device__ __forceinline__ void mma_tf32(float* c, uint32_t a0, uint32_t a1,
                                         uint32_t a2, uint32_t a3,
                                         uint32_t b0, uint32_t b1) {
    asm volatile(
        "mma.sync.aligned.m16n8k8.row.col.f32.tf32.tf32.f32 "
        "{%0,%1,%2,%3}, {%4,%5,%6,%7}, {%8,%9}, {%0,%1,%2,%3};"
        : "+f"(c[0]), "+f"(c[1]), "+f"(c[2]), "+f"(c[3])
        : "r"(a0), "r"(a1), "r"(a2), "r"(a3), "r"(b0), "r"(b1));
}

// ---------- Kernel 0: weights -> tf32 fragments (grid = 8 x 4) ----------
__global__ __launch_bounds__(256) void wprep_k(const float* __restrict__ weight) {
    const int t = blockIdx.x;
    const int part = blockIdx.y;
    for (int it = part * 9; it < part * 9 + 9; it++) {
        const int j = it * 256 + threadIdx.x;        // j < 9216
        const int reg   = j & 1;
        const int lane  = (j >> 1) & 31;
        const int ntile = (j >> 6) & 3;
        const int kstep = (j >> 8) & 3;
        const int tap   = j >> 10;
        const int cin  = kstep * 8 + (lane & 3) + reg * 4;
        const int cout = ntile * 8 + (lane >> 2);
        const float v = weight[((size_t)(t * Cc + cout) * Cc + cin) * KK + tap];
        g_wfrag[(size_t)t * 9216 + j] = f2tf32(v);
    }
}

// ---------- Kernel 1: feat [B,C,T,H,W] fp32 -> scratch [B,T,HW,C] fp16 ----------
__global__ __launch_bounds__(256) void transpose_k(const float* __restrict__ feat) {
    __shared__ float tl[32][33];
    const int bt = blockIdx.y;
    const int b = bt >> 3, t = bt & 7;
    const int hw0 = blockIdx.x * 32;
    const int x = threadIdx.x & 31;
    const int y = threadIdx.x >> 5;
    #pragma unroll
    for (int j = 0; j < 4; j++) {
        const int c = y + j * 8;
        tl[c][x] = feat[((size_t)(b * Cc + c) * Tt + t) * HWsz + hw0 + x];
    }
    __syncthreads();
    // Write packed half2: 32 hw x 16 half2 = 512 stores, 2 per thread.
    uint32_t* gdst = (uint32_t*)g_scratch_h + ((size_t)bt * HWsz + hw0) * 16;
    #pragma unroll
    for (int it = 0; it < 2; it++) {
        const int idx = it * 256 + threadIdx.x;   // 0..511
        const int hwl = idx >> 4;
        const int cp  = idx & 15;                 // channel pair
        const __half2 h = __floats2half2_rn(tl[2 * cp][hwl], tl[2 * cp + 1][hwl]);
        gdst[hwl * 16 + cp] = *(const uint32_t*)&h;
    }
}

// ---------- Kernel 2: fused deform-sample + mma.sync tf32 GEMM ----------
#define SM_W 0
#define SM_A 36864
#define SM_TOTAL 73728
#define APAD 36
#define DPAD 260

__global__ __launch_bounds__(256, 2) void dcn_main(
    const float* __restrict__ offset,   // [B, 18, T, H, W]
    float* __restrict__ out)            // [B, 32, T, H, W]
{
    extern __shared__ char smem[];
    uint32_t* swf = (uint32_t*)(smem + SM_W);
    const int tid  = threadIdx.x;
    const int wid  = tid >> 5;
    const int lane = tid & 31;
    const int bt = blockIdx.y;
    const int b = bt >> 3, t = bt & 7;
    const int pix0  = blockIdx.x * 256;
    const int pixw0 = pix0 + wid * 32;

    // Copy this t's weight fragments (9216 u32) to smem, coalesced.
    {
        const uint4* src = (const uint4*)(g_wfrag + (size_t)t * 9216);
        uint4* dst = (uint4*)swf;
        #pragma unroll
        for (int i = 0; i < 9; i++) dst[tid + 256 * i] = src[tid + 256 * i];
    }
    __syncthreads();

    uint32_t* sa = (uint32_t*)(smem + SM_A) + wid * (32 * APAD);  // warp-private A slab
    // fp16 scratch: pixel row = 8 uint2 (64B); this lane covers channels (lane&7)*4..+3
    const uint2* sbase = (const uint2*)g_scratch_h + (size_t)bt * HWsz * 8 + (lane & 7);
    const float* offb = offset + ((size_t)b * 2 * KK * Tt + t) * HWsz + pixw0;

    float acc[2][4][4];
    #pragma unroll
    for (int s = 0; s < 2; s++)
        #pragma unroll
        for (int n = 0; n < 4; n++)
            #pragma unroll
            for (int r = 0; r < 4; r++) acc[s][n][r] = 0.f;

    #pragma unroll 1
    for (int k = 0; k < KK; k++) {
        const float odyv = offb[(size_t)(2 * k)     * Tt * HWsz + lane];
        const float odxv = offb[(size_t)(2 * k + 1) * Tt * HWsz + lane];
        const int dky = k / 3 - 1;
        const int dkx = k - (k / 3) * 3 - 1;

        #pragma unroll 2
        for (int p = 0; p < 8; p++) {
            const int pixl = p * 4 + (lane >> 3);
            const int pixg = pixw0 + pixl;
            const int h = (int)((unsigned)pixg / Ww);
            const int w = pixg - h * Ww;

            const float dy = __shfl_sync(0xffffffffu, odyv, pixl);
            const float dx = __shfl_sync(0xffffffffu, odxv, pixl);
            const float ys = dy + (float)(h + dky);
            const float xs = dx + (float)(w + dkx);

            const float y0f = floorf(ys), x0f = floorf(xs);
            const int iy0 = (int)y0f, ix0 = (int)x0f;
            const int iy1 = iy0 + 1,  ix1 = ix0 + 1;
            const float fy = ys - y0f, fx = xs - x0f;
            const float gy = 1.f - fy, gx = 1.f - fx;

            const bool vy0 = (unsigned)iy0 < Hh;
            const bool vy1 = (unsigned)iy1 < Hh;
            const bool vx0 = (unsigned)ix0 < Ww;
            const bool vx1 = (unsigned)ix1 < Ww;
            const int cy0 = min(max(iy0, 0), Hh - 1);
            const int cy1 = min(max(iy1, 0), Hh - 1);
            const int cx0 = min(max(ix0, 0), Ww - 1);
            const int cx1 = min(max(ix1, 0), Ww - 1);

            const float w00 = (vy0 && vx0) ? gy * gx : 0.f;
            const float w01 = (vy0 && vx1) ? gy * fx : 0.f;
            const float w10 = (vy1 && vx0) ? fy * gx : 0.f;
            const float w11 = (vy1 && vx1) ? fy * fx : 0.f;

            const uint2 q00 = sbase[(size_t)(cy0 * Ww + cx0) * 8];
            const uint2 q01 = sbase[(size_t)(cy0 * Ww + cx1) * 8];
            const uint2 q10 = sbase[(size_t)(cy1 * Ww + cx0) * 8];
            const uint2 q11 = sbase[(size_t)(cy1 * Ww + cx1) * 8];

            const float2 a00l = __half22float2(*(const __half2*)&q00.x);
            const float2 a00h = __half22float2(*(const __half2*)&q00.y);
            const float2 a01l = __half22float2(*(const __half2*)&q01.x);
            const float2 a01h = __half22float2(*(const __half2*)&q01.y);
            const float2 a10l = __half22float2(*(const __half2*)&q10.x);
            const float2 a10h = __half22float2(*(const __half2*)&q10.y);
            const float2 a11l = __half22float2(*(const __half2*)&q11.x);
            const float2 a11h = __half22float2(*(const __half2*)&q11.y);

            const float v0 = fmaf(w00, a00l.x, fmaf(w01, a01l.x, fmaf(w10, a10l.x, w11 * a11l.x)));
            const float v1 = fmaf(w00, a00l.y, fmaf(w01, a01l.y, fmaf(w10, a10l.y, w11 * a11l.y)));
            const float v2 = fmaf(w00, a00h.x, fmaf(w01, a01h.x, fmaf(w10, a10h.x, w11 * a11h.x)));
            const float v3 = fmaf(w00, a00h.y, fmaf(w01, a01h.y, fmaf(w10, a10h.y, w11 * a11h.y)));

            uint4 u; u.x = f2tf32(v0); u.y = f2tf32(v1); u.z = f2tf32(v2); u.w = f2tf32(v3);
            *(uint4*)(sa + pixl * APAD + (lane & 7) * 4) = u;
        }
        __syncwarp();

        // ---- MMA: D[32x32] += A[32x32] * W_k^T ----
        const int r0 = lane >> 2;
        const int c0 = lane & 3;
        #pragma unroll
        for (int ks = 0; ks < 4; ks++) {
            const int cb = ks * 8 + c0;
            const uint32_t a00_ = sa[r0 * APAD + cb];
            const uint32_t a01_ = sa[(r0 + 8) * APAD + cb];
            const uint32_t a02_ = sa[r0 * APAD + cb + 4];
            const uint32_t a03_ = sa[(r0 + 8) * APAD + cb + 4];
            const uint32_t a10_ = sa[(r0 + 16) * APAD + cb];
            const uint32_t a11_ = sa[(r0 + 24) * APAD + cb];
            const uint32_t a12_ = sa[(r0 + 16) * APAD + cb + 4];
            const uint32_t a13_ = sa[(r0 + 24) * APAD + cb + 4];
            #pragma unroll
            for (int nt = 0; nt < 4; nt++) {
                const uint2 bb = *(const uint2*)(swf + (((k * 4 + ks) * 4 + nt) << 6) + lane * 2);
                mma_tf32(acc[0][nt], a00_, a01_, a02_, a03_, bb.x, bb.y);
                mma_tf32(acc[1][nt], a10_, a11_, a12_, a13_, bb.x, bb.y);
            }
        }
        __syncwarp();
    }

    // Epilogue: stage D in smem (reusing A region), then coalesced STG.128.
    __syncthreads();
    float* sd = (float*)(smem + SM_A);
    {
        const int pixb = wid * 32 + (lane >> 2);
        #pragma unroll
        for (int s = 0; s < 2; s++) {
            #pragma unroll
            for (int nt = 0; nt < 4; nt++) {
                const int row = nt * 8 + 2 * (lane & 3);
                const int px = pixb + s * 16;
                sd[row * DPAD + px]           = acc[s][nt][0];
                sd[(row + 1) * DPAD + px]     = acc[s][nt][1];
                sd[row * DPAD + px + 8]       = acc[s][nt][2];
                sd[(row + 1) * DPAD + px + 8] = acc[s][nt][3];
            }
        }
    }
    __syncthreads();
    #pragma unroll
    for (int i = 0; i < 8; i++) {
        const int j = tid + 256 * i;
        const int row = j >> 6;            // cout
        const int q = j & 63;              // float4 index within 256 pixels
        const float4 v = *(const float4*)(sd + row * DPAD + q * 4);
        *(float4*)(out + ((size_t)(b * Cc + row) * Tt + t) * HWsz + pix0 + q * 4) = v;
    }
}

extern "C" void kernel_launch(void* const* d_in, const int* in_sizes, int n_in,
                              void* d_out, int out_size) {
    const float* feat   = (const float*)d_in[0];
    const float* offset = (const float*)d_in[1];
    const float* weight = (const float*)d_in[2];
    float* out = (float*)d_out;

    cudaFuncSetAttribute(dcn_main, cudaFuncAttributeMaxDynamicSharedMemorySize, SM_TOTAL);

    wprep_k<<<dim3(Tt, 4), 256>>>(weight);
    transpose_k<<<dim3(HWsz / 32, 16), 256>>>(feat);
    dcn_main<<<dim3(HWsz / 256, 16), 256, SM_TOTAL>>>(offset, out);
}

// round 7
// speedup vs baseline: 1.2123x; 1.1226x over previous
#include <cuda_runtime.h>
#include <cuda_fp16.h>
#include <cstdint>

#define Hh 192
#define Ww 192
#define HWsz (192*192)
#define Cc 32
#define Tt 8
#define KK 9

// Channels-last fp16 scratch: [B][T][HW][C]  (37.7 MB)
__device__ __half g_scratch_h[(size_t)2 * Tt * HWsz * Cc];
// Weights in mma fragment order: [t][tap][kstep][ntile][lane][reg]
__device__ uint32_t g_wfrag[(size_t)Tt * KK * 4 * 4 * 32 * 2];

__device__ __forceinline__ uint32_t f2tf32(float v) {
    uint32_t u;
    asm("cvt.rna.tf32.f32 %0, %1;" : "=r"(u) : "f"(v));
    return u;
}

__device__ __forceinline__ void mma_tf32(float* c, uint32_t a0, uint32_t a1,
                                         uint32_t a2, uint32_t a3,
                                         uint32_t b0, uint32_t b1) {
    asm volatile(
        "mma.sync.aligned.m16n8k8.row.col.f32.tf32.tf32.f32 "
        "{%0,%1,%2,%3}, {%4,%5,%6,%7}, {%8,%9}, {%0,%1,%2,%3};"
        : "+f"(c[0]), "+f"(c[1]), "+f"(c[2]), "+f"(c[3])
        : "r"(a0), "r"(a1), "r"(a2), "r"(a3), "r"(b0), "r"(b1));
}

// ---------- Kernel 0: weights -> tf32 fragments (grid = 8 x 4) ----------
__global__ __launch_bounds__(256) void wprep_k(const float* __restrict__ weight) {
    const int t = blockIdx.x;
    const int part = blockIdx.y;
    for (int it = part * 9; it < part * 9 + 9; it++) {
        const int j = it * 256 + threadIdx.x;        // j < 9216
        const int reg   = j & 1;
        const int lane  = (j >> 1) & 31;
        const int ntile = (j >> 6) & 3;
        const int kstep = (j >> 8) & 3;
        const int tap   = j >> 10;
        const int cin  = kstep * 8 + (lane & 3) + reg * 4;
        const int cout = ntile * 8 + (lane >> 2);
        const float v = weight[((size_t)(t * Cc + cout) * Cc + cin) * KK + tap];
        g_wfrag[(size_t)t * 9216 + j] = f2tf32(v);
    }
}

// ---------- Kernel 1: feat [B,C,T,H,W] fp32 -> scratch [B,T,HW,C] fp16 ----------
__global__ __launch_bounds__(256) void transpose_k(const float* __restrict__ feat) {
    __shared__ float tl[32][33];
    const int bt = blockIdx.y;
    const int b = bt >> 3, t = bt & 7;
    const int hw0 = blockIdx.x * 32;
    const int x = threadIdx.x & 31;
    const int y = threadIdx.x >> 5;
    #pragma unroll
    for (int j = 0; j < 4; j++) {
        const int c = y + j * 8;
        tl[c][x] = feat[((size_t)(b * Cc + c) * Tt + t) * HWsz + hw0 + x];
    }
    __syncthreads();
    uint32_t* gdst = (uint32_t*)g_scratch_h + ((size_t)bt * HWsz + hw0) * 16;
    #pragma unroll
    for (int it = 0; it < 2; it++) {
        const int idx = it * 256 + threadIdx.x;   // 0..511
        const int hwl = idx >> 4;
        const int cp  = idx & 15;                 // channel pair
        const __half2 h = __floats2half2_rn(tl[2 * cp][hwl], tl[2 * cp + 1][hwl]);
        gdst[hwl * 16 + cp] = *(const uint32_t*)&h;
    }
}

// ---------- Kernel 2: fused deform-sample + mma.sync tf32 GEMM ----------
// smem: A slabs 8 x 32x36 floats = 36864B (reused as Dtile 32x260 in epilogue)
#define SM_TOTAL 36864
#define APAD 36
#define DPAD 260

__global__ __launch_bounds__(256, 3) void dcn_main(
    const float* __restrict__ offset,   // [B, 18, T, H, W]
    float* __restrict__ out)            // [B, 32, T, H, W]
{
    extern __shared__ char smem[];
    const int tid  = threadIdx.x;
    const int wid  = tid >> 5;
    const int lane = tid & 31;
    const int bt = blockIdx.y;
    const int b = bt >> 3, t = bt & 7;
    const int pix0  = blockIdx.x * 256;
    const int pixw0 = pix0 + wid * 32;

    uint32_t* sa = (uint32_t*)smem + wid * (32 * APAD);  // warp-private A slab
    const uint2* sbase = (const uint2*)g_scratch_h + (size_t)bt * HWsz * 8 + (lane & 7);
    const float* offb = offset + ((size_t)b * 2 * KK * Tt + t) * HWsz + pixw0;
    const uint32_t* gwf = g_wfrag + (size_t)t * 9216 + lane * 2;  // B frags, from L1

    float acc[2][4][4];
    #pragma unroll
    for (int s = 0; s < 2; s++)
        #pragma unroll
        for (int n = 0; n < 4; n++)
            #pragma unroll
            for (int r = 0; r < 4; r++) acc[s][n][r] = 0.f;

    #pragma unroll 1
    for (int k = 0; k < KK; k++) {
        const float odyv = offb[(size_t)(2 * k)     * Tt * HWsz + lane];
        const float odxv = offb[(size_t)(2 * k + 1) * Tt * HWsz + lane];
        const int dky = k / 3 - 1;
        const int dkx = k - (k / 3) * 3 - 1;

        #pragma unroll 2
        for (int p = 0; p < 8; p++) {
            const int pixl = p * 4 + (lane >> 3);
            const int pixg = pixw0 + pixl;
            const int h = (int)((unsigned)pixg / Ww);
            const int w = pixg - h * Ww;

            const float dy = __shfl_sync(0xffffffffu, odyv, pixl);
            const float dx = __shfl_sync(0xffffffffu, odxv, pixl);
            const float ys = dy + (float)(h + dky);
            const float xs = dx + (float)(w + dkx);

            const float y0f = floorf(ys), x0f = floorf(xs);
            const int iy0 = (int)y0f, ix0 = (int)x0f;
            const int iy1 = iy0 + 1,  ix1 = ix0 + 1;
            const float fy = ys - y0f, fx = xs - x0f;
            const float gy = 1.f - fy, gx = 1.f - fx;

            const bool vy0 = (unsigned)iy0 < Hh;
            const bool vy1 = (unsigned)iy1 < Hh;
            const bool vx0 = (unsigned)ix0 < Ww;
            const bool vx1 = (unsigned)ix1 < Ww;
            const int cy0 = min(max(iy0, 0), Hh - 1);
            const int cy1 = min(max(iy1, 0), Hh - 1);
            const int cx0 = min(max(ix0, 0), Ww - 1);
            const int cx1 = min(max(ix1, 0), Ww - 1);

            const float w00 = (vy0 && vx0) ? gy * gx : 0.f;
            const float w01 = (vy0 && vx1) ? gy * fx : 0.f;
            const float w10 = (vy1 && vx0) ? fy * gx : 0.f;
            const float w11 = (vy1 && vx1) ? fy * fx : 0.f;

            const uint2 q00 = sbase[(size_t)(cy0 * Ww + cx0) * 8];
            const uint2 q01 = sbase[(size_t)(cy0 * Ww + cx1) * 8];
            const uint2 q10 = sbase[(size_t)(cy1 * Ww + cx0) * 8];
            const uint2 q11 = sbase[(size_t)(cy1 * Ww + cx1) * 8];

            const float2 a00l = __half22float2(*(const __half2*)&q00.x);
            const float2 a00h = __half22float2(*(const __half2*)&q00.y);
            const float2 a01l = __half22float2(*(const __half2*)&q01.x);
            const float2 a01h = __half22float2(*(const __half2*)&q01.y);
            const float2 a10l = __half22float2(*(const __half2*)&q10.x);
            const float2 a10h = __half22float2(*(const __half2*)&q10.y);
            const float2 a11l = __half22float2(*(const __half2*)&q11.x);
            const float2 a11h = __half22float2(*(const __half2*)&q11.y);

            const float v0 = fmaf(w00, a00l.x, fmaf(w01, a01l.x, fmaf(w10, a10l.x, w11 * a11l.x)));
            const float v1 = fmaf(w00, a00l.y, fmaf(w01, a01l.y, fmaf(w10, a10l.y, w11 * a11l.y)));
            const float v2 = fmaf(w00, a00h.x, fmaf(w01, a01h.x, fmaf(w10, a10h.x, w11 * a11h.x)));
            const float v3 = fmaf(w00, a00h.y, fmaf(w01, a01h.y, fmaf(w10, a10h.y, w11 * a11h.y)));

            uint4 u; u.x = f2tf32(v0); u.y = f2tf32(v1); u.z = f2tf32(v2); u.w = f2tf32(v3);
            *(uint4*)(sa + pixl * APAD + (lane & 7) * 4) = u;
        }
        __syncwarp();

        // ---- MMA: D[32x32] += A[32x32] * W_k^T; B frags streamed from L1 ----
        const int r0 = lane >> 2;
        const int c0 = lane & 3;
        #pragma unroll
        for (int ks = 0; ks < 4; ks++) {
            const int cb = ks * 8 + c0;
            const uint32_t a00_ = sa[r0 * APAD + cb];
            const uint32_t a01_ = sa[(r0 + 8) * APAD + cb];
            const uint32_t a02_ = sa[r0 * APAD + cb + 4];
            const uint32_t a03_ = sa[(r0 + 8) * APAD + cb + 4];
            const uint32_t a10_ = sa[(r0 + 16) * APAD + cb];
            const uint32_t a11_ = sa[(r0 + 24) * APAD + cb];
            const uint32_t a12_ = sa[(r0 + 16) * APAD + cb + 4];
            const uint32_t a13_ = sa[(r0 + 24) * APAD + cb + 4];
            #pragma unroll
            for (int nt = 0; nt < 4; nt++) {
                const uint2 bb = __ldg((const uint2*)(gwf + (((k * 4 + ks) * 4 + nt) << 6)));
                mma_tf32(acc[0][nt], a00_, a01_, a02_, a03_, bb.x, bb.y);
                mma_tf32(acc[1][nt], a10_, a11_, a12_, a13_, bb.x, bb.y);
            }
        }
        __syncwarp();
    }

    // Epilogue: stage D in smem (reusing A region), then coalesced STG.128.
    __syncthreads();
    float* sd = (float*)smem;
    {
        const int pixb = wid * 32 + (lane >> 2);
        #pragma unroll
        for (int s = 0; s < 2; s++) {
            #pragma unroll
            for (int nt = 0; nt < 4; nt++) {
                const int row = nt * 8 + 2 * (lane & 3);
                const int px = pixb + s * 16;
                sd[row * DPAD + px]           = acc[s][nt][0];
                sd[(row + 1) * DPAD + px]     = acc[s][nt][1];
                sd[row * DPAD + px + 8]       = acc[s][nt][2];
                sd[(row + 1) * DPAD + px + 8] = acc[s][nt][3];
            }
        }
    }
    __syncthreads();
    #pragma unroll
    for (int i = 0; i < 8; i++) {
        const int j = tid + 256 * i;
        const int row = j >> 6;            // cout
        const int q = j & 63;              // float4 index within 256 pixels
        const float4 v = *(const float4*)(sd + row * DPAD + q * 4);
        *(float4*)(out + ((size_t)(b * Cc + row) * Tt + t) * HWsz + pix0 + q * 4) = v;
    }
}

extern "C" void kernel_launch(void* const* d_in, const int* in_sizes, int n_in,
                              void* d_out, int out_size) {
    const float* feat   = (const float*)d_in[0];
    const float* offset = (const float*)d_in[1];
    const float* weight = (const float*)d_in[2];
    float* out = (float*)d_out;

    cudaFuncSetAttribute(dcn_main, cudaFuncAttributeMaxDynamicSharedMemorySize, SM_TOTAL);

    wprep_k<<<dim3(Tt, 4), 256>>>(weight);
    transpose_k<<<dim3(HWsz / 32, 16), 256>>>(feat);
    dcn_main<<<dim3(HWsz / 256, 16), 256, SM_TOTAL>>>(offset, out);
}